// round 7
// baseline (speedup 1.0000x reference)
#include <cuda_runtime.h>
#include <math.h>

#define NU 100000
#define NI 50000
#define NN (NU + NI)            // 150000 nodes
#define DIM 64
#define NE 1250000
#define NALL (NN * DIM)         // 9,600,000 floats per buffer

#define SCAN_B 1024
#define NBLK ((NN + SCAN_B - 1) / SCAN_B)   // 147

// Scratch (allocation-free): ~166 MB of __device__ globals.
__device__ __align__(16) float g_b[4][NALL];  // b0=emb, b1..b3 = layer outputs
__device__ int       g_degi[NN];              // in-degree (int)
__device__ int       g_rowstart[NN + 1];      // CSR row offsets (by dst)
__device__ int       g_rowfill[NN];           // fill cursors
__device__ int       g_blocksum[NBLK];        // scan partials
__device__ __align__(8) long long g_csr[NE];  // packed (norm<<32 | soff)

// ---------------------------------------------------------------------------
// K0: b0 = concat(user, item); zero degree + fill cursors.
__global__ void k_init(const float* __restrict__ uw, const float* __restrict__ iw) {
    int i = blockIdx.x * blockDim.x + threadIdx.x;
    if (i < NALL) {
        int row = i >> 6;
        g_b[0][i] = (row < NU) ? uw[i] : iw[i - NU * DIM];
    }
    if (i < NN) { g_degi[i] = 0; g_rowfill[i] = 0; }
}

// K1: in-degree (int). edge_index is int32 (JAX x64-off). Bounds-guarded.
__global__ void k_deg(const int* __restrict__ ei) {
    int e = blockIdx.x * blockDim.x + threadIdx.x;
    if (e >= NE) return;
    int dst = ei[NE + e];
    if ((unsigned)dst < (unsigned)NN) atomicAdd(&g_degi[dst], 1);
}

// K2a: per-1024-block exclusive scan of degrees; emit block sums.
__global__ void k_scan1() {
    __shared__ int s[SCAN_B];
    int i = blockIdx.x * SCAN_B + threadIdx.x;
    int v = (i < NN) ? g_degi[i] : 0;
    s[threadIdx.x] = v;
    __syncthreads();
    for (int off = 1; off < SCAN_B; off <<= 1) {
        int t = (threadIdx.x >= off) ? s[threadIdx.x - off] : 0;
        __syncthreads();
        s[threadIdx.x] += t;
        __syncthreads();
    }
    if (i < NN) g_rowstart[i] = s[threadIdx.x] - v;  // exclusive within block
    if (threadIdx.x == SCAN_B - 1) g_blocksum[blockIdx.x] = s[SCAN_B - 1];
}

// K2b: each block reduces its own prefix of the <=147 block sums locally
// (replaces the old serial single-block scan2 + scan3 pair).
__global__ void k_scan3() {
    __shared__ int s[256];
    int b = blockIdx.x;                      // which 1024-node region
    int t = threadIdx.x;
    // threads 0..255 cover all <=147 block sums
    int v = (t < b && t < NBLK) ? g_blocksum[t] : 0;
    s[t & 255] = 0;
    __syncthreads();
    if (t < 256) s[t] = v;
    __syncthreads();
    for (int off = 128; off > 0; off >>= 1) {
        if (t < off) s[t] += s[t + off];
        __syncthreads();
    }
    int offset = s[0];
    for (int k = t; k < SCAN_B; k += blockDim.x) {
        int i = b * SCAN_B + k;
        if (i < NN) g_rowstart[i] += offset;
    }
    if (b == 0 && t == 0) g_rowstart[NN] = NE;
}

// K3: compute norms and fill CSR with packed 8-byte records.
__global__ void k_fill(const int* __restrict__ ei) {
    int e = blockIdx.x * blockDim.x + threadIdx.x;
    if (e >= NE) return;
    int src = ei[e];
    int dst = ei[NE + e];
    if ((unsigned)dst >= (unsigned)NN) return;   // consistent with k_deg guard
    bool sok = (unsigned)src < (unsigned)NN;
    int ds = sok ? g_degi[src] : 0;
    int dd = g_degi[dst];
    float n = 0.0f;
    if (ds > 0 && dd > 0)
        n = 1.0f / (sqrtf((float)ds) * sqrtf((float)dd));
    int soff = sok ? (src << 6) : 0;
    int pos = g_rowstart[dst] + atomicAdd(&g_rowfill[dst], 1);
    long long pk = ((long long)__float_as_int(n) << 32) | (unsigned)soff;
    g_csr[pos] = pk;
}

#define DECODE(pk, s, n) { s = (int)(unsigned)(pk); n = __int_as_float((int)((pk) >> 32)); }

// K4/5: pull layer. One 16-lane group per dst row, one float4 chunk per lane.
// 4-way unrolled edge loop: one LDG.64 metadata + one vec4 gather per edge.
__global__ void k_gather(int lin, int lout) {
    int g = blockIdx.x * 16 + (threadIdx.x >> 4);
    if (g >= NN) return;
    int lane = (threadIdx.x & 15) << 2;
    const float* __restrict__ in = g_b[lin];
    int p   = g_rowstart[g];
    int end = g_rowstart[g + 1];
    float ax = 0.f, ay = 0.f, az = 0.f, aw = 0.f;
    for (; p + 4 <= end; p += 4) {
        long long m0 = g_csr[p],     m1 = g_csr[p + 1];
        long long m2 = g_csr[p + 2], m3 = g_csr[p + 3];
        int s0, s1, s2, s3; float n0, n1, n2, n3;
        DECODE(m0, s0, n0); DECODE(m1, s1, n1);
        DECODE(m2, s2, n2); DECODE(m3, s3, n3);
        float4 v0 = *reinterpret_cast<const float4*>(&in[s0 + lane]);
        float4 v1 = *reinterpret_cast<const float4*>(&in[s1 + lane]);
        float4 v2 = *reinterpret_cast<const float4*>(&in[s2 + lane]);
        float4 v3 = *reinterpret_cast<const float4*>(&in[s3 + lane]);
        ax += n0 * v0.x; ay += n0 * v0.y; az += n0 * v0.z; aw += n0 * v0.w;
        ax += n1 * v1.x; ay += n1 * v1.y; az += n1 * v1.z; aw += n1 * v1.w;
        ax += n2 * v2.x; ay += n2 * v2.y; az += n2 * v2.z; aw += n2 * v2.w;
        ax += n3 * v3.x; ay += n3 * v3.y; az += n3 * v3.z; aw += n3 * v3.w;
    }
    for (; p < end; ++p) {
        long long m0 = g_csr[p];
        int s0; float n0; DECODE(m0, s0, n0);
        float4 v0 = *reinterpret_cast<const float4*>(&in[s0 + lane]);
        ax += n0 * v0.x; ay += n0 * v0.y; az += n0 * v0.z; aw += n0 * v0.w;
    }
    *reinterpret_cast<float4*>(&g_b[lout][(g << 6) + lane]) =
        make_float4(ax, ay, az, aw);
}

// K6: layer-3 gather fused with the final average + duplicated output write.
// out layout [all; user; item] == [all; all] (contiguous, same row order).
__global__ void k_gather_final(float* __restrict__ out) {
    int g = blockIdx.x * 16 + (threadIdx.x >> 4);
    if (g >= NN) return;
    int lane = (threadIdx.x & 15) << 2;
    const float* __restrict__ in = g_b[2];   // layer-2 output
    int p   = g_rowstart[g];
    int end = g_rowstart[g + 1];
    float ax = 0.f, ay = 0.f, az = 0.f, aw = 0.f;
    for (; p + 4 <= end; p += 4) {
        long long m0 = g_csr[p],     m1 = g_csr[p + 1];
        long long m2 = g_csr[p + 2], m3 = g_csr[p + 3];
        int s0, s1, s2, s3; float n0, n1, n2, n3;
        DECODE(m0, s0, n0); DECODE(m1, s1, n1);
        DECODE(m2, s2, n2); DECODE(m3, s3, n3);
        float4 v0 = *reinterpret_cast<const float4*>(&in[s0 + lane]);
        float4 v1 = *reinterpret_cast<const float4*>(&in[s1 + lane]);
        float4 v2 = *reinterpret_cast<const float4*>(&in[s2 + lane]);
        float4 v3 = *reinterpret_cast<const float4*>(&in[s3 + lane]);
        ax += n0 * v0.x; ay += n0 * v0.y; az += n0 * v0.z; aw += n0 * v0.w;
        ax += n1 * v1.x; ay += n1 * v1.y; az += n1 * v1.z; aw += n1 * v1.w;
        ax += n2 * v2.x; ay += n2 * v2.y; az += n2 * v2.z; aw += n2 * v2.w;
        ax += n3 * v3.x; ay += n3 * v3.y; az += n3 * v3.z; aw += n3 * v3.w;
    }
    for (; p < end; ++p) {
        long long m0 = g_csr[p];
        int s0; float n0; DECODE(m0, s0, n0);
        float4 v0 = *reinterpret_cast<const float4*>(&in[s0 + lane]);
        ax += n0 * v0.x; ay += n0 * v0.y; az += n0 * v0.z; aw += n0 * v0.w;
    }
    int i = (g << 6) + lane;
    float4 b0 = *reinterpret_cast<const float4*>(&g_b[0][i]);
    float4 b1 = *reinterpret_cast<const float4*>(&g_b[1][i]);
    float4 b2 = *reinterpret_cast<const float4*>(&g_b[2][i]);
    float4 v = make_float4(0.25f * (b0.x + b1.x + b2.x + ax),
                           0.25f * (b0.y + b1.y + b2.y + ay),
                           0.25f * (b0.z + b1.z + b2.z + az),
                           0.25f * (b0.w + b1.w + b2.w + aw));
    *reinterpret_cast<float4*>(&out[i]) = v;
    *reinterpret_cast<float4*>(&out[NALL + i]) = v;
}

extern "C" void kernel_launch(void* const* d_in, const int* in_sizes, int n_in,
                              void* d_out, int out_size) {
    const int*   ei = (const int*)d_in[0];      // [2, NE] int32
    const float* uw = (const float*)d_in[1];    // [NU, 64]
    const float* iw = (const float*)d_in[2];    // [NI, 64]
    float*      out = (float*)d_out;            // [2*NALL] floats

    const int T = 256;
    int g_nall = (NALL + T - 1) / T;
    int g_edge = (NE + T - 1) / T;
    int g_gath = (NN + 15) / 16;                // 16 row-groups per block

    k_init<<<g_nall, T>>>(uw, iw);
    k_deg<<<g_edge, T>>>(ei);
    k_scan1<<<NBLK, SCAN_B>>>();
    k_scan3<<<NBLK, 256>>>();
    k_fill<<<g_edge, T>>>(ei);

    k_gather<<<g_gath, T>>>(0, 1);   // layer 1
    k_gather<<<g_gath, T>>>(1, 2);   // layer 2
    k_gather_final<<<g_gath, T>>>(out);  // layer 3 + average + dup write
}

// round 8
// speedup vs baseline: 1.5988x; 1.5988x over previous
#include <cuda_runtime.h>
#include <cuda_fp16.h>
#include <math.h>

#define NU 100000
#define NI 50000
#define NN (NU + NI)            // 150000 nodes
#define DIM 64
#define NE 1250000
#define NALL (NN * DIM)         // 9,600,000 elements per buffer

#define SCAN_B 1024
#define NBLK ((NN + SCAN_B - 1) / SCAN_B)   // 147

// Scratch (allocation-free): ~100 MB of __device__ globals.
// Layer buffers in fp16: halves gather bytes, all 4 buffers L2-resident.
__device__ __align__(16) __half g_h[4][NALL]; // h0=emb(fp16), h1..h3 layers
__device__ int       g_degi[NN];              // in-degree
__device__ int       g_rowstart[NN];          // CSR row base (by dst)
__device__ int       g_rowfill[NN];           // fill cursors
__device__ int       g_ctr;                   // global range allocator
__device__ __align__(8) long long g_csr[NE];  // packed (norm<<32 | src*64)

// ---------------------------------------------------------------------------
// K0: h0 = fp16(concat(user, item)); zero counters.
__global__ void k_init(const float* __restrict__ uw, const float* __restrict__ iw) {
    int i = blockIdx.x * blockDim.x + threadIdx.x;
    if (i < NALL) {
        int row = i >> 6;
        float v = (row < NU) ? uw[i] : iw[i - NU * DIM];
        g_h[0][i] = __float2half_rn(v);
    }
    if (i < NN) { g_degi[i] = 0; g_rowfill[i] = 0; }
    if (i == 0) g_ctr = 0;
}

// K1: in-degree. edge_index is int32 (JAX x64-off). Bounds-guarded.
__global__ void k_deg(const int* __restrict__ ei) {
    int e = blockIdx.x * blockDim.x + threadIdx.x;
    if (e >= NE) return;
    int dst = ei[NE + e];
    if ((unsigned)dst < (unsigned)NN) atomicAdd(&g_degi[dst], 1);
}

// K2: CSR range allocation. Shuffle-based block exclusive scan of degrees;
// ONE atomicAdd per block grabs the block's contiguous range (row placement
// order is arbitrary — only per-row contiguity matters for the gather).
__global__ void k_alloc() {
    __shared__ int warpsum[32];
    __shared__ int s_base;
    int i = blockIdx.x * SCAN_B + threadIdx.x;
    int lane = threadIdx.x & 31;
    int wid  = threadIdx.x >> 5;
    int v = (i < NN) ? g_degi[i] : 0;
    int x = v;                                   // inclusive warp scan
    #pragma unroll
    for (int off = 1; off < 32; off <<= 1) {
        int t = __shfl_up_sync(0xFFFFFFFFu, x, off);
        if (lane >= off) x += t;
    }
    if (lane == 31) warpsum[wid] = x;
    __syncthreads();
    if (threadIdx.x < 32) {
        int w = warpsum[threadIdx.x];
        int y = w;
        #pragma unroll
        for (int off = 1; off < 32; off <<= 1) {
            int t = __shfl_up_sync(0xFFFFFFFFu, y, off);
            if (threadIdx.x >= off) y += t;
        }
        warpsum[threadIdx.x] = y - w;            // exclusive
        if (threadIdx.x == 31) s_base = atomicAdd(&g_ctr, y);  // block total
    }
    __syncthreads();
    if (i < NN) g_rowstart[i] = s_base + warpsum[wid] + (x - v);
}

// K3: compute norms, fill CSR with packed 8-byte (norm, src*64) records.
__global__ void k_fill(const int* __restrict__ ei) {
    int e = blockIdx.x * blockDim.x + threadIdx.x;
    if (e >= NE) return;
    int src = ei[e];
    int dst = ei[NE + e];
    if ((unsigned)dst >= (unsigned)NN) return;   // consistent with k_deg
    bool sok = (unsigned)src < (unsigned)NN;
    int ds = sok ? g_degi[src] : 0;
    int dd = g_degi[dst];
    float n = 0.0f;
    if (ds > 0 && dd > 0)
        n = 1.0f / (sqrtf((float)ds) * sqrtf((float)dd));
    int soff = sok ? (src << 6) : 0;
    int pos = g_rowstart[dst] + atomicAdd(&g_rowfill[dst], 1);
    g_csr[pos] = ((long long)__float_as_int(n) << 32) | (unsigned)soff;
}

#define DECODE(pk, s, n) { s = (int)(unsigned)(pk); n = __int_as_float((int)((pk) >> 32)); }

// Per-edge fp16 gather body: one uint4 = 8 halves = 16B, fp32 accumulate.
#define EDGE(M) {                                                          \
    int s_; float n_; DECODE(M, s_, n_);                                   \
    uint4 r_ = *reinterpret_cast<const uint4*>(&in[s_ + le]);              \
    float2 f_;                                                             \
    f_ = __half22float2(*reinterpret_cast<__half2*>(&r_.x));               \
    a0 += n_ * f_.x; a1 += n_ * f_.y;                                      \
    f_ = __half22float2(*reinterpret_cast<__half2*>(&r_.y));               \
    a2 += n_ * f_.x; a3 += n_ * f_.y;                                      \
    f_ = __half22float2(*reinterpret_cast<__half2*>(&r_.z));               \
    a4 += n_ * f_.x; a5 += n_ * f_.y;                                      \
    f_ = __half22float2(*reinterpret_cast<__half2*>(&r_.w));               \
    a6 += n_ * f_.x; a7 += n_ * f_.y; }

// K4/5: pull layer. 8 lanes per dst row (16B of fp16 each), 4 rows per warp
// -> one LDG.128 warp-instruction services 4 edges. fp32 accum, fp16 store.
__global__ void k_gather(int lin, int lout) {
    int g = blockIdx.x * 32 + (threadIdx.x >> 3);
    if (g >= NN) return;
    int le = (threadIdx.x & 7) << 3;             // element offset in row
    const __half* __restrict__ in = g_h[lin];
    int p   = g_rowstart[g];
    int end = p + g_degi[g];
    float a0=0,a1=0,a2=0,a3=0,a4=0,a5=0,a6=0,a7=0;
    for (; p + 4 <= end; p += 4) {
        long long m0 = g_csr[p],     m1 = g_csr[p + 1];
        long long m2 = g_csr[p + 2], m3 = g_csr[p + 3];
        EDGE(m0) EDGE(m1) EDGE(m2) EDGE(m3)
    }
    for (; p < end; ++p) { long long m0 = g_csr[p]; EDGE(m0) }
    __half2 p01 = __floats2half2_rn(a0, a1), p23 = __floats2half2_rn(a2, a3);
    __half2 p45 = __floats2half2_rn(a4, a5), p67 = __floats2half2_rn(a6, a7);
    uint4 o;
    o.x = *reinterpret_cast<unsigned*>(&p01);
    o.y = *reinterpret_cast<unsigned*>(&p23);
    o.z = *reinterpret_cast<unsigned*>(&p45);
    o.w = *reinterpret_cast<unsigned*>(&p67);
    *reinterpret_cast<uint4*>(&g_h[lout][(g << 6) + le]) = o;
}

// K6: layer-3 gather fused with final average. Layer-0 term read from the
// fp32 originals (exact). out layout [all; user; item] == [all; all].
__global__ void k_gather_final(const float* __restrict__ uw,
                               const float* __restrict__ iw,
                               float* __restrict__ out) {
    int g = blockIdx.x * 32 + (threadIdx.x >> 3);
    if (g >= NN) return;
    int le = (threadIdx.x & 7) << 3;
    const __half* __restrict__ in = g_h[2];
    int p   = g_rowstart[g];
    int end = p + g_degi[g];
    float a0=0,a1=0,a2=0,a3=0,a4=0,a5=0,a6=0,a7=0;
    for (; p + 4 <= end; p += 4) {
        long long m0 = g_csr[p],     m1 = g_csr[p + 1];
        long long m2 = g_csr[p + 2], m3 = g_csr[p + 3];
        EDGE(m0) EDGE(m1) EDGE(m2) EDGE(m3)
    }
    for (; p < end; ++p) { long long m0 = g_csr[p]; EDGE(m0) }

    int i = (g << 6) + le;
    const float* emb = (g < NU) ? &uw[i] : &iw[i - NU * DIM];
    float4 e0 = *reinterpret_cast<const float4*>(emb);
    float4 e1 = *reinterpret_cast<const float4*>(emb + 4);
    uint4 r1 = *reinterpret_cast<const uint4*>(&g_h[1][i]);
    uint4 r2 = *reinterpret_cast<const uint4*>(&g_h[2][i]);
    float2 f1a = __half22float2(*reinterpret_cast<__half2*>(&r1.x));
    float2 f1b = __half22float2(*reinterpret_cast<__half2*>(&r1.y));
    float2 f1c = __half22float2(*reinterpret_cast<__half2*>(&r1.z));
    float2 f1d = __half22float2(*reinterpret_cast<__half2*>(&r1.w));
    float2 f2a = __half22float2(*reinterpret_cast<__half2*>(&r2.x));
    float2 f2b = __half22float2(*reinterpret_cast<__half2*>(&r2.y));
    float2 f2c = __half22float2(*reinterpret_cast<__half2*>(&r2.z));
    float2 f2d = __half22float2(*reinterpret_cast<__half2*>(&r2.w));
    float4 v0 = make_float4(0.25f * (e0.x + f1a.x + f2a.x + a0),
                            0.25f * (e0.y + f1a.y + f2a.y + a1),
                            0.25f * (e0.z + f1b.x + f2b.x + a2),
                            0.25f * (e0.w + f1b.y + f2b.y + a3));
    float4 v1 = make_float4(0.25f * (e1.x + f1c.x + f2c.x + a4),
                            0.25f * (e1.y + f1c.y + f2c.y + a5),
                            0.25f * (e1.z + f1d.x + f2d.x + a6),
                            0.25f * (e1.w + f1d.y + f2d.y + a7));
    *reinterpret_cast<float4*>(&out[i])            = v0;
    *reinterpret_cast<float4*>(&out[i + 4])        = v1;
    *reinterpret_cast<float4*>(&out[NALL + i])     = v0;
    *reinterpret_cast<float4*>(&out[NALL + i + 4]) = v1;
}

extern "C" void kernel_launch(void* const* d_in, const int* in_sizes, int n_in,
                              void* d_out, int out_size) {
    const int*   ei = (const int*)d_in[0];      // [2, NE] int32
    const float* uw = (const float*)d_in[1];    // [NU, 64]
    const float* iw = (const float*)d_in[2];    // [NI, 64]
    float*      out = (float*)d_out;            // [2*NALL] floats

    const int T = 256;
    int g_nall = (NALL + T - 1) / T;
    int g_edge = (NE + T - 1) / T;
    int g_gath = (NN + 31) / 32;                // 32 rows per 256-thread block

    k_init<<<g_nall, T>>>(uw, iw);
    k_deg<<<g_edge, T>>>(ei);
    k_alloc<<<NBLK, SCAN_B>>>();
    k_fill<<<g_edge, T>>>(ei);

    k_gather<<<g_gath, T>>>(0, 1);            // layer 1
    k_gather<<<g_gath, T>>>(1, 2);            // layer 2
    k_gather_final<<<g_gath, T>>>(uw, iw, out); // layer 3 + average + dup
}

// round 10
// speedup vs baseline: 1.6571x; 1.0364x over previous
#include <cuda_runtime.h>
#include <cuda_fp16.h>
#include <math.h>

#define NU 100000
#define NI 50000
#define NN (NU + NI)            // 150000 nodes
#define DIM 64
#define NE 1250000
#define NALL (NN * DIM)         // 9,600,000 elements per buffer

#define SCAN_B 1024
#define NBLK ((NN + SCAN_B - 1) / SCAN_B)   // 147

// Scratch (allocation-free): ~100 MB of __device__ globals.
__device__ __align__(16) __half g_h[4][NALL]; // h0=emb(fp16), h1..h3 layers
__device__ int       g_degi[NN];              // in-degree
__device__ int       g_rowstart[NN];          // CSR cursor: start -> end
__device__ float     g_rns[NN];               // rsqrt(deg) or 0
__device__ int       g_ctr;                   // global range allocator
__device__ __align__(8) long long g_csr[NE];  // packed (norm<<32 | src*64)

// ---------------------------------------------------------------------------
// K0: zero degree + allocator (must precede the fused init/deg kernel).
__global__ void k_zero() {
    int i = blockIdx.x * blockDim.x + threadIdx.x;
    if (i < NN) g_degi[i] = 0;
    if (i == 0) g_ctr = 0;
}

// K1: fused — h0 = fp16(concat(user,item)) AND in-degree accumulation.
// Streaming convert and L2 atomics use different pipes; they overlap.
__global__ void k_initdeg(const float* __restrict__ uw,
                          const float* __restrict__ iw,
                          const int* __restrict__ ei) {
    int i = blockIdx.x * blockDim.x + threadIdx.x;
    if (i < NALL) {
        int row = i >> 6;
        float v = (row < NU) ? uw[i] : iw[i - NU * DIM];
        g_h[0][i] = __float2half_rn(v);
    }
    if (i < NE) {
        int dst = ei[NE + i];                 // int32 (JAX x64-off)
        if ((unsigned)dst < (unsigned)NN) atomicAdd(&g_degi[dst], 1);
    }
}

// K2: CSR range allocation (shuffle block-scan + one atomic per block) and
// per-node rsqrt(deg) precompute (degi already in registers — free).
__global__ void k_alloc() {
    __shared__ int warpsum[32];
    __shared__ int s_base;
    int i = blockIdx.x * SCAN_B + threadIdx.x;
    int lane = threadIdx.x & 31;
    int wid  = threadIdx.x >> 5;
    int v = (i < NN) ? g_degi[i] : 0;
    if (i < NN) g_rns[i] = (v > 0) ? rsqrtf((float)v) : 0.0f;
    int x = v;                                   // inclusive warp scan
    #pragma unroll
    for (int off = 1; off < 32; off <<= 1) {
        int t = __shfl_up_sync(0xFFFFFFFFu, x, off);
        if (lane >= off) x += t;
    }
    if (lane == 31) warpsum[wid] = x;
    __syncthreads();
    if (threadIdx.x < 32) {
        int w = warpsum[threadIdx.x];
        int y = w;
        #pragma unroll
        for (int off = 1; off < 32; off <<= 1) {
            int t = __shfl_up_sync(0xFFFFFFFFu, y, off);
            if (threadIdx.x >= off) y += t;
        }
        warpsum[threadIdx.x] = y - w;            // exclusive
        if (threadIdx.x == 31) s_base = atomicAdd(&g_ctr, y);  // block total
    }
    __syncthreads();
    if (i < NN) g_rowstart[i] = s_base + warpsum[wid] + (x - v);
}

// K3: fill CSR. rowstart doubles as the cursor (atomic returns the slot and
// leaves rowstart[dst] == row end). norm = rns[src]*rns[dst], one FMUL.
__global__ void k_fill(const int* __restrict__ ei) {
    int e = blockIdx.x * blockDim.x + threadIdx.x;
    if (e >= NE) return;
    int src = ei[e];
    int dst = ei[NE + e];
    if ((unsigned)dst >= (unsigned)NN) return;   // consistent with deg guard
    bool sok = (unsigned)src < (unsigned)NN;
    float n = sok ? g_rns[src] * g_rns[dst] : 0.0f;  // deg0 src -> rns=0 -> 0
    int soff = sok ? (src << 6) : 0;
    int pos = atomicAdd(&g_rowstart[dst], 1);
    g_csr[pos] = ((long long)__float_as_int(n) << 32) | (unsigned)soff;
}

#define DECODE(pk, s, n) { s = (int)(unsigned)(pk); n = __int_as_float((int)((pk) >> 32)); }

// Per-edge fp16 gather body: one uint4 = 8 halves = 16B, fp32 accumulate.
#define EDGE(M) {                                                          \
    int s_; float n_; DECODE(M, s_, n_);                                   \
    uint4 r_ = *reinterpret_cast<const uint4*>(&in[s_ + le]);              \
    float2 f_;                                                             \
    f_ = __half22float2(*reinterpret_cast<__half2*>(&r_.x));               \
    a0 += n_ * f_.x; a1 += n_ * f_.y;                                      \
    f_ = __half22float2(*reinterpret_cast<__half2*>(&r_.y));               \
    a2 += n_ * f_.x; a3 += n_ * f_.y;                                      \
    f_ = __half22float2(*reinterpret_cast<__half2*>(&r_.z));               \
    a4 += n_ * f_.x; a5 += n_ * f_.y;                                      \
    f_ = __half22float2(*reinterpret_cast<__half2*>(&r_.w));               \
    a6 += n_ * f_.x; a7 += n_ * f_.y; }

// K4/5: pull layer. 8 lanes per dst row (16B fp16 each), 4 rows per warp.
// Row range: end = rowstart[g] (post-fill), start = end - degi[g].
__global__ void k_gather(int lin, int lout) {
    int g = blockIdx.x * 32 + (threadIdx.x >> 3);
    if (g >= NN) return;
    int le = (threadIdx.x & 7) << 3;
    const __half* __restrict__ in = g_h[lin];
    int end = g_rowstart[g];
    int p   = end - g_degi[g];
    float a0=0,a1=0,a2=0,a3=0,a4=0,a5=0,a6=0,a7=0;
    for (; p + 4 <= end; p += 4) {
        long long m0 = g_csr[p],     m1 = g_csr[p + 1];
        long long m2 = g_csr[p + 2], m3 = g_csr[p + 3];
        EDGE(m0) EDGE(m1) EDGE(m2) EDGE(m3)
    }
    for (; p < end; ++p) { long long m0 = g_csr[p]; EDGE(m0) }
    __half2 p01 = __floats2half2_rn(a0, a1), p23 = __floats2half2_rn(a2, a3);
    __half2 p45 = __floats2half2_rn(a4, a5), p67 = __floats2half2_rn(a6, a7);
    uint4 o;
    o.x = *reinterpret_cast<unsigned*>(&p01);
    o.y = *reinterpret_cast<unsigned*>(&p23);
    o.z = *reinterpret_cast<unsigned*>(&p45);
    o.w = *reinterpret_cast<unsigned*>(&p67);
    *reinterpret_cast<uint4*>(&g_h[lout][(g << 6) + le]) = o;
}

// K6: layer-3 gather fused with final average. Layer-0 term read from the
// fp32 originals (exact). out layout [all; user; item] == [all; all].
__global__ void k_gather_final(const float* __restrict__ uw,
                               const float* __restrict__ iw,
                               float* __restrict__ out) {
    int g = blockIdx.x * 32 + (threadIdx.x >> 3);
    if (g >= NN) return;
    int le = (threadIdx.x & 7) << 3;
    const __half* __restrict__ in = g_h[2];
    int end = g_rowstart[g];
    int p   = end - g_degi[g];
    float a0=0,a1=0,a2=0,a3=0,a4=0,a5=0,a6=0,a7=0;
    for (; p + 4 <= end; p += 4) {
        long long m0 = g_csr[p],     m1 = g_csr[p + 1];
        long long m2 = g_csr[p + 2], m3 = g_csr[p + 3];
        EDGE(m0) EDGE(m1) EDGE(m2) EDGE(m3)
    }
    for (; p < end; ++p) { long long m0 = g_csr[p]; EDGE(m0) }

    int i = (g << 6) + le;
    const float* emb = (g < NU) ? &uw[i] : &iw[i - NU * DIM];
    float4 e0 = *reinterpret_cast<const float4*>(emb);
    float4 e1 = *reinterpret_cast<const float4*>(emb + 4);
    uint4 r1 = *reinterpret_cast<const uint4*>(&g_h[1][i]);
    uint4 r2 = *reinterpret_cast<const uint4*>(&g_h[2][i]);
    float2 f1a = __half22float2(*reinterpret_cast<__half2*>(&r1.x));
    float2 f1b = __half22float2(*reinterpret_cast<__half2*>(&r1.y));
    float2 f1c = __half22float2(*reinterpret_cast<__half2*>(&r1.z));
    float2 f1d = __half22float2(*reinterpret_cast<__half2*>(&r1.w));
    float2 f2a = __half22float2(*reinterpret_cast<__half2*>(&r2.x));
    float2 f2b = __half22float2(*reinterpret_cast<__half2*>(&r2.y));
    float2 f2c = __half22float2(*reinterpret_cast<__half2*>(&r2.z));
    float2 f2d = __half22float2(*reinterpret_cast<__half2*>(&r2.w));
    float4 v0 = make_float4(0.25f * (e0.x + f1a.x + f2a.x + a0),
                            0.25f * (e0.y + f1a.y + f2a.y + a1),
                            0.25f * (e0.z + f1b.x + f2b.x + a2),
                            0.25f * (e0.w + f1b.y + f2b.y + a3));
    float4 v1 = make_float4(0.25f * (e1.x + f1c.x + f2c.x + a4),
                            0.25f * (e1.y + f1c.y + f2c.y + a5),
                            0.25f * (e1.z + f1d.x + f2d.x + a6),
                            0.25f * (e1.w + f1d.y + f2d.y + a7));
    *reinterpret_cast<float4*>(&out[i])            = v0;
    *reinterpret_cast<float4*>(&out[i + 4])        = v1;
    *reinterpret_cast<float4*>(&out[NALL + i])     = v0;
    *reinterpret_cast<float4*>(&out[NALL + i + 4]) = v1;
}

extern "C" void kernel_launch(void* const* d_in, const int* in_sizes, int n_in,
                              void* d_out, int out_size) {
    const int*   ei = (const int*)d_in[0];      // [2, NE] int32
    const float* uw = (const float*)d_in[1];    // [NU, 64]
    const float* iw = (const float*)d_in[2];    // [NI, 64]
    float*      out = (float*)d_out;            // [2*NALL] floats

    const int T = 256;
    int g_nall = (NALL + T - 1) / T;
    int g_edge = (NE + T - 1) / T;
    int g_node = (NN + T - 1) / T;
    int g_gath = (NN + 31) / 32;                // 32 rows per 256-thread block

    k_zero<<<g_node, T>>>();
    k_initdeg<<<g_nall, T>>>(uw, iw, ei);
    k_alloc<<<NBLK, SCAN_B>>>();
    k_fill<<<g_edge, T>>>(ei);

    k_gather<<<g_gath, T>>>(0, 1);              // layer 1
    k_gather<<<g_gath, T>>>(1, 2);              // layer 2
    k_gather_final<<<g_gath, T>>>(uw, iw, out); // layer 3 + average + dup
}

// round 12
// speedup vs baseline: 1.8605x; 1.1227x over previous
#include <cuda_runtime.h>
#include <cuda_fp16.h>
#include <math.h>

#define NU 100000
#define NI 50000
#define NN (NU + NI)            // 150000 nodes
#define DIM 64
#define NE 1250000
#define NALL (NN * DIM)         // 9,600,000 elements per buffer

#define SCAN_B 1024
#define NBLK ((NN + SCAN_B - 1) / SCAN_B)   // 147

// Scratch (allocation-free): ~63 MB of __device__ globals.
// s_l = rns .* cur_l  (pre-scaled layer buffers, fp16). One sentinel row at
// index NN (always zero) absorbs invalid-src edges.
__device__ __align__(16) __half g_s[3][NALL + DIM];
__device__ int   g_degi[NN];      // in-degree
__device__ int   g_rowstart[NN];  // CSR cursor: start -> end (post-fill)
__device__ float g_rns[NN];       // 1/sqrt(deg) or 0
__device__ float g_inv[NN];       // sqrt(deg) or 0
__device__ int   g_ctr;           // global range allocator
__device__ int   g_csr[NE];       // src*64 (or NN*64 sentinel)

// ---------------------------------------------------------------------------
// K0: zero degree, allocator, and the sentinel rows of all s-buffers.
__global__ void k_zero() {
    int i = blockIdx.x * blockDim.x + threadIdx.x;
    if (i < NN) g_degi[i] = 0;
    if (i == 0) g_ctr = 0;
    if (i < DIM) {
        g_s[0][NALL + i] = __float2half_rn(0.0f);
        g_s[1][NALL + i] = __float2half_rn(0.0f);
        g_s[2][NALL + i] = __float2half_rn(0.0f);
    }
}

// K1: in-degree. edge_index is int32 (JAX x64-off). Bounds-guarded.
__global__ void k_deg(const int* __restrict__ ei) {
    int e = blockIdx.x * blockDim.x + threadIdx.x;
    if (e >= NE) return;
    int dst = ei[NE + e];
    if ((unsigned)dst < (unsigned)NN) atomicAdd(&g_degi[dst], 1);
}

// K2: CSR range allocation (shuffle block-scan + one atomic per block);
// also precompute rns = 1/sqrt(deg) and inv = sqrt(deg) (0 for deg==0).
__global__ void k_alloc() {
    __shared__ int warpsum[32];
    __shared__ int s_base;
    int i = blockIdx.x * SCAN_B + threadIdx.x;
    int lane = threadIdx.x & 31;
    int wid  = threadIdx.x >> 5;
    int v = (i < NN) ? g_degi[i] : 0;
    if (i < NN) {
        g_rns[i] = (v > 0) ? rsqrtf((float)v) : 0.0f;
        g_inv[i] = (v > 0) ? sqrtf((float)v)  : 0.0f;
    }
    int x = v;                                   // inclusive warp scan
    #pragma unroll
    for (int off = 1; off < 32; off <<= 1) {
        int t = __shfl_up_sync(0xFFFFFFFFu, x, off);
        if (lane >= off) x += t;
    }
    if (lane == 31) warpsum[wid] = x;
    __syncthreads();
    if (threadIdx.x < 32) {
        int w = warpsum[threadIdx.x];
        int y = w;
        #pragma unroll
        for (int off = 1; off < 32; off <<= 1) {
            int t = __shfl_up_sync(0xFFFFFFFFu, y, off);
            if (threadIdx.x >= off) y += t;
        }
        warpsum[threadIdx.x] = y - w;            // exclusive
        if (threadIdx.x == 31) s_base = atomicAdd(&g_ctr, y);
    }
    __syncthreads();
    if (i < NN) g_rowstart[i] = s_base + warpsum[wid] + (x - v);
}

// K3: s0 = fp16(rns[row] * emb) — fused convert + pre-scale.
__global__ void k_scale0(const float* __restrict__ uw, const float* __restrict__ iw) {
    int i = blockIdx.x * blockDim.x + threadIdx.x;
    if (i >= NALL) return;
    int row = i >> 6;
    float v = (row < NU) ? uw[i] : iw[i - NU * DIM];
    g_s[0][i] = __float2half_rn(v * g_rns[row]);
}

// K4: fill CSR (4B payload: src*64; invalid src -> sentinel row NN).
// rowstart doubles as cursor: atomic leaves rowstart[dst] == row end.
__global__ void k_fill(const int* __restrict__ ei) {
    int e = blockIdx.x * blockDim.x + threadIdx.x;
    if (e >= NE) return;
    int src = ei[e];
    int dst = ei[NE + e];
    if ((unsigned)dst >= (unsigned)NN) return;   // consistent with deg guard
    int soff = ((unsigned)src < (unsigned)NN) ? (src << 6) : (NN << 6);
    int pos = atomicAdd(&g_rowstart[dst], 1);
    g_csr[pos] = soff;
}

// Pure-sum edge body: one uint4 = 8 halves, half2 accumulate (4 HADD2).
#define EDGE(S, A0, A1, A2, A3) {                                          \
    uint4 r_ = *reinterpret_cast<const uint4*>(&in[(S) + le]);             \
    A0 = __hadd2(A0, *reinterpret_cast<__half2*>(&r_.x));                  \
    A1 = __hadd2(A1, *reinterpret_cast<__half2*>(&r_.y));                  \
    A2 = __hadd2(A2, *reinterpret_cast<__half2*>(&r_.z));                  \
    A3 = __hadd2(A3, *reinterpret_cast<__half2*>(&r_.w)); }

// K5/6: pull layer (pure sum), then s_out[d] = rns[d]^2 * t.
// 8 lanes per row (16B fp16 each), 4 rows per warp. Two alternating
// accumulator sets (pairwise accuracy + ILP), fp32 combine in epilogue.
__global__ void k_gather(int lin, int lout) {
    int g = blockIdx.x * 32 + (threadIdx.x >> 3);
    if (g >= NN) return;
    int le = (threadIdx.x & 7) << 3;
    const __half* __restrict__ in = g_s[lin];
    int end = g_rowstart[g];
    int p   = end - g_degi[g];
    __half2 z = __float2half2_rn(0.0f);
    __half2 pA0=z,pA1=z,pA2=z,pA3=z, pB0=z,pB1=z,pB2=z,pB3=z;
    for (; p + 4 <= end; p += 4) {
        int s0 = g_csr[p],     s1 = g_csr[p + 1];
        int s2 = g_csr[p + 2], s3 = g_csr[p + 3];
        EDGE(s0, pA0, pA1, pA2, pA3) EDGE(s1, pB0, pB1, pB2, pB3)
        EDGE(s2, pA0, pA1, pA2, pA3) EDGE(s3, pB0, pB1, pB2, pB3)
    }
    for (; p < end; ++p) { int s0 = g_csr[p]; EDGE(s0, pA0, pA1, pA2, pA3) }
    float r = g_rns[g]; float r2 = r * r;
    float2 fA, fB;
    fA = __half22float2(pA0); fB = __half22float2(pB0);
    __half2 o0 = __floats2half2_rn(r2 * (fA.x + fB.x), r2 * (fA.y + fB.y));
    fA = __half22float2(pA1); fB = __half22float2(pB1);
    __half2 o1 = __floats2half2_rn(r2 * (fA.x + fB.x), r2 * (fA.y + fB.y));
    fA = __half22float2(pA2); fB = __half22float2(pB2);
    __half2 o2 = __floats2half2_rn(r2 * (fA.x + fB.x), r2 * (fA.y + fB.y));
    fA = __half22float2(pA3); fB = __half22float2(pB3);
    __half2 o3 = __floats2half2_rn(r2 * (fA.x + fB.x), r2 * (fA.y + fB.y));
    uint4 o;
    o.x = *reinterpret_cast<unsigned*>(&o0);
    o.y = *reinterpret_cast<unsigned*>(&o1);
    o.z = *reinterpret_cast<unsigned*>(&o2);
    o.w = *reinterpret_cast<unsigned*>(&o3);
    *reinterpret_cast<uint4*>(&g_s[lout][(g << 6) + le]) = o;
}

// K7: layer-3 gather fused with final average.
// out = 0.25*(emb_fp32 + inv*(s1+s2) + rns*t3); inv*s_l == cur_l exactly.
// out layout [all; user; item] == [all; all].
__global__ void k_gather_final(const float* __restrict__ uw,
                               const float* __restrict__ iw,
                               float* __restrict__ out) {
    int g = blockIdx.x * 32 + (threadIdx.x >> 3);
    if (g >= NN) return;
    int le = (threadIdx.x & 7) << 3;
    const __half* __restrict__ in = g_s[2];
    int end = g_rowstart[g];
    int p   = end - g_degi[g];
    __half2 z = __float2half2_rn(0.0f);
    __half2 pA0=z,pA1=z,pA2=z,pA3=z, pB0=z,pB1=z,pB2=z,pB3=z;
    for (; p + 4 <= end; p += 4) {
        int s0 = g_csr[p],     s1 = g_csr[p + 1];
        int s2 = g_csr[p + 2], s3 = g_csr[p + 3];
        EDGE(s0, pA0, pA1, pA2, pA3) EDGE(s1, pB0, pB1, pB2, pB3)
        EDGE(s2, pA0, pA1, pA2, pA3) EDGE(s3, pB0, pB1, pB2, pB3)
    }
    for (; p < end; ++p) { int s0 = g_csr[p]; EDGE(s0, pA0, pA1, pA2, pA3) }

    float r   = g_rns[g];          // rns[d]
    float inv = g_inv[g];          // sqrt(deg) (0 if deg==0)
    int i = (g << 6) + le;
    const float* emb = (g < NU) ? &uw[i] : &iw[i - NU * DIM];
    float4 e0 = *reinterpret_cast<const float4*>(emb);
    float4 e1 = *reinterpret_cast<const float4*>(emb + 4);
    uint4 r1 = *reinterpret_cast<const uint4*>(&g_s[1][i]);
    uint4 r2 = *reinterpret_cast<const uint4*>(&g_s[2][i]);
    float2 s1a = __half22float2(*reinterpret_cast<__half2*>(&r1.x));
    float2 s1b = __half22float2(*reinterpret_cast<__half2*>(&r1.y));
    float2 s1c = __half22float2(*reinterpret_cast<__half2*>(&r1.z));
    float2 s1d = __half22float2(*reinterpret_cast<__half2*>(&r1.w));
    float2 s2a = __half22float2(*reinterpret_cast<__half2*>(&r2.x));
    float2 s2b = __half22float2(*reinterpret_cast<__half2*>(&r2.y));
    float2 s2c = __half22float2(*reinterpret_cast<__half2*>(&r2.z));
    float2 s2d = __half22float2(*reinterpret_cast<__half2*>(&r2.w));
    float2 tA, tB;
    tA = __half22float2(pA0); tB = __half22float2(pB0);
    float t0 = tA.x + tB.x, t1 = tA.y + tB.y;
    tA = __half22float2(pA1); tB = __half22float2(pB1);
    float t2 = tA.x + tB.x, t3 = tA.y + tB.y;
    tA = __half22float2(pA2); tB = __half22float2(pB2);
    float t4 = tA.x + tB.x, t5 = tA.y + tB.y;
    tA = __half22float2(pA3); tB = __half22float2(pB3);
    float t6 = tA.x + tB.x, t7 = tA.y + tB.y;
    float4 v0 = make_float4(0.25f * (e0.x + inv * (s1a.x + s2a.x) + r * t0),
                            0.25f * (e0.y + inv * (s1a.y + s2a.y) + r * t1),
                            0.25f * (e0.z + inv * (s1b.x + s2b.x) + r * t2),
                            0.25f * (e0.w + inv * (s1b.y + s2b.y) + r * t3));
    float4 v1 = make_float4(0.25f * (e1.x + inv * (s1c.x + s2c.x) + r * t4),
                            0.25f * (e1.y + inv * (s1c.y + s2c.y) + r * t5),
                            0.25f * (e1.z + inv * (s1d.x + s2d.x) + r * t6),
                            0.25f * (e1.w + inv * (s1d.y + s2d.y) + r * t7));
    *reinterpret_cast<float4*>(&out[i])            = v0;
    *reinterpret_cast<float4*>(&out[i + 4])        = v1;
    *reinterpret_cast<float4*>(&out[NALL + i])     = v0;
    *reinterpret_cast<float4*>(&out[NALL + i + 4]) = v1;
}

extern "C" void kernel_launch(void* const* d_in, const int* in_sizes, int n_in,
                              void* d_out, int out_size) {
    const int*   ei = (const int*)d_in[0];      // [2, NE] int32
    const float* uw = (const float*)d_in[1];    // [NU, 64]
    const float* iw = (const float*)d_in[2];    // [NI, 64]
    float*      out = (float*)d_out;            // [2*NALL] floats

    const int T = 256;
    int g_nall = (NALL + T - 1) / T;
    int g_edge = (NE + T - 1) / T;
    int g_node = (NN + T - 1) / T;
    int g_gath = (NN + 31) / 32;                // 32 rows per 256-thread block

    k_zero<<<g_node, T>>>();
    k_deg<<<g_edge, T>>>(ei);
    k_alloc<<<NBLK, SCAN_B>>>();
    k_scale0<<<g_nall, T>>>(uw, iw);
    k_fill<<<g_edge, T>>>(ei);

    k_gather<<<g_gath, T>>>(0, 1);              // layer 1: s0 -> s1
    k_gather<<<g_gath, T>>>(1, 2);              // layer 2: s1 -> s2
    k_gather_final<<<g_gath, T>>>(uw, iw, out); // layer 3 + average + dup
}

// round 14
// speedup vs baseline: 2.2071x; 1.1863x over previous
#include <cuda_runtime.h>
#include <cuda_fp16.h>
#include <math.h>

#define NU 100000
#define NI 50000
#define NN (NU + NI)            // 150000 nodes
#define DIM 64
#define NE 1250000
#define NALL (NN * DIM)         // 9,600,000 elements per buffer
#define NV8 (NALL / 8)          // 1,200,000 8-element vector units

#define SCAN_B 1024
#define NBLK ((NN + SCAN_B - 1) / SCAN_B)   // 147

// Scratch (allocation-free): ~63 MB of __device__ globals.
// s_l = rns .* cur_l  (pre-scaled layer buffers, fp16). One sentinel row at
// index NN (always zero) absorbs invalid-src edges.
__device__ __align__(16) __half g_s[3][NALL + DIM];
__device__ int   g_degi[NN];      // in-degree
__device__ int   g_rowstart[NN];  // CSR cursor: start -> end (post-fill)
__device__ float g_rns[NN];       // 1/sqrt(deg) or 0
__device__ float g_inv[NN];       // sqrt(deg) or 0
__device__ int   g_ctr;           // global range allocator
__device__ int   g_csr[NE];       // src*64 (or NN*64 sentinel)

// ---------------------------------------------------------------------------
// K0: zero degree, allocator, and the sentinel rows of all s-buffers.
__global__ void k_zero() {
    int i = blockIdx.x * blockDim.x + threadIdx.x;
    if (i < NN) g_degi[i] = 0;
    if (i == 0) g_ctr = 0;
    if (i < DIM) {
        g_s[0][NALL + i] = __float2half_rn(0.0f);
        g_s[1][NALL + i] = __float2half_rn(0.0f);
        g_s[2][NALL + i] = __float2half_rn(0.0f);
    }
}

// K1: in-degree. edge_index is int32 (JAX x64-off). Bounds-guarded.
__global__ void k_deg(const int* __restrict__ ei) {
    int e = blockIdx.x * blockDim.x + threadIdx.x;
    if (e >= NE) return;
    int dst = ei[NE + e];
    if ((unsigned)dst < (unsigned)NN) atomicAdd(&g_degi[dst], 1);
}

// K2: CSR range allocation (shuffle block-scan + one atomic per block);
// also precompute rns = 1/sqrt(deg) and inv = sqrt(deg) (0 for deg==0).
__global__ void k_alloc() {
    __shared__ int warpsum[32];
    __shared__ int s_base;
    int i = blockIdx.x * SCAN_B + threadIdx.x;
    int lane = threadIdx.x & 31;
    int wid  = threadIdx.x >> 5;
    int v = (i < NN) ? g_degi[i] : 0;
    if (i < NN) {
        g_rns[i] = (v > 0) ? rsqrtf((float)v) : 0.0f;
        g_inv[i] = (v > 0) ? sqrtf((float)v)  : 0.0f;
    }
    int x = v;                                   // inclusive warp scan
    #pragma unroll
    for (int off = 1; off < 32; off <<= 1) {
        int t = __shfl_up_sync(0xFFFFFFFFu, x, off);
        if (lane >= off) x += t;
    }
    if (lane == 31) warpsum[wid] = x;
    __syncthreads();
    if (threadIdx.x < 32) {
        int w = warpsum[threadIdx.x];
        int y = w;
        #pragma unroll
        for (int off = 1; off < 32; off <<= 1) {
            int t = __shfl_up_sync(0xFFFFFFFFu, y, off);
            if (threadIdx.x >= off) y += t;
        }
        warpsum[threadIdx.x] = y - w;            // exclusive
        if (threadIdx.x == 31) s_base = atomicAdd(&g_ctr, y);
    }
    __syncthreads();
    if (i < NN) g_rowstart[i] = s_base + warpsum[wid] + (x - v);
}

// K3: FUSED fill + pre-scale.
//  - fill side (tid < NE): CSR fill, random L2 atomics (4B payload).
//  - scale side (tid < NV8): s0 = fp16(rns*emb), 8 elems/thread, vectorized
//    (float4 x2 load, one rns per 8, uint4 store). Disjoint HW resources
//    (L2-atomic vs DRAM-stream) -> the two halves overlap.
__global__ void k_fillscale(const int* __restrict__ ei,
                            const float* __restrict__ uw,
                            const float* __restrict__ iw) {
    int tid = blockIdx.x * blockDim.x + threadIdx.x;
    if (tid < NE) {
        int src = ei[tid];
        int dst = ei[NE + tid];
        if ((unsigned)dst < (unsigned)NN) {      // consistent with deg guard
            int soff = ((unsigned)src < (unsigned)NN) ? (src << 6) : (NN << 6);
            int pos = atomicAdd(&g_rowstart[dst], 1);
            g_csr[pos] = soff;
        }
    }
    if (tid < NV8) {
        int base = tid << 3;                     // 8 elems, all in one row
        int row  = base >> 6;
        float r = g_rns[row];
        const float* emb = (row < NU) ? &uw[base] : &iw[base - NU * DIM];
        float4 e0 = *reinterpret_cast<const float4*>(emb);
        float4 e1 = *reinterpret_cast<const float4*>(emb + 4);
        __half2 h0 = __floats2half2_rn(r * e0.x, r * e0.y);
        __half2 h1 = __floats2half2_rn(r * e0.z, r * e0.w);
        __half2 h2 = __floats2half2_rn(r * e1.x, r * e1.y);
        __half2 h3 = __floats2half2_rn(r * e1.z, r * e1.w);
        uint4 o;
        o.x = *reinterpret_cast<unsigned*>(&h0);
        o.y = *reinterpret_cast<unsigned*>(&h1);
        o.z = *reinterpret_cast<unsigned*>(&h2);
        o.w = *reinterpret_cast<unsigned*>(&h3);
        *reinterpret_cast<uint4*>(&g_s[0][base]) = o;
    }
}

// Pure-sum edge body: one uint4 = 8 halves, half2 accumulate (4 HADD2).
#define EDGE(S, A0, A1, A2, A3) {                                          \
    uint4 r_ = *reinterpret_cast<const uint4*>(&in[(S) + le]);             \
    A0 = __hadd2(A0, *reinterpret_cast<__half2*>(&r_.x));                  \
    A1 = __hadd2(A1, *reinterpret_cast<__half2*>(&r_.y));                  \
    A2 = __hadd2(A2, *reinterpret_cast<__half2*>(&r_.z));                  \
    A3 = __hadd2(A3, *reinterpret_cast<__half2*>(&r_.w)); }

// K4/5: pull layer (pure sum), then s_out[d] = rns[d]^2 * t.
// 8 lanes per row (16B fp16 each), 4 rows per warp. Two alternating
// accumulator sets (pairwise accuracy + ILP), fp32 combine in epilogue.
__global__ void k_gather(int lin, int lout) {
    int g = blockIdx.x * 32 + (threadIdx.x >> 3);
    if (g >= NN) return;
    int le = (threadIdx.x & 7) << 3;
    const __half* __restrict__ in = g_s[lin];
    int end = g_rowstart[g];
    int p   = end - g_degi[g];
    __half2 z = __float2half2_rn(0.0f);
    __half2 pA0=z,pA1=z,pA2=z,pA3=z, pB0=z,pB1=z,pB2=z,pB3=z;
    for (; p + 4 <= end; p += 4) {
        int s0 = g_csr[p],     s1 = g_csr[p + 1];
        int s2 = g_csr[p + 2], s3 = g_csr[p + 3];
        EDGE(s0, pA0, pA1, pA2, pA3) EDGE(s1, pB0, pB1, pB2, pB3)
        EDGE(s2, pA0, pA1, pA2, pA3) EDGE(s3, pB0, pB1, pB2, pB3)
    }
    for (; p < end; ++p) { int s0 = g_csr[p]; EDGE(s0, pA0, pA1, pA2, pA3) }
    float r = g_rns[g]; float r2 = r * r;
    float2 fA, fB;
    fA = __half22float2(pA0); fB = __half22float2(pB0);
    __half2 o0 = __floats2half2_rn(r2 * (fA.x + fB.x), r2 * (fA.y + fB.y));
    fA = __half22float2(pA1); fB = __half22float2(pB1);
    __half2 o1 = __floats2half2_rn(r2 * (fA.x + fB.x), r2 * (fA.y + fB.y));
    fA = __half22float2(pA2); fB = __half22float2(pB2);
    __half2 o2 = __floats2half2_rn(r2 * (fA.x + fB.x), r2 * (fA.y + fB.y));
    fA = __half22float2(pA3); fB = __half22float2(pB3);
    __half2 o3 = __floats2half2_rn(r2 * (fA.x + fB.x), r2 * (fA.y + fB.y));
    uint4 o;
    o.x = *reinterpret_cast<unsigned*>(&o0);
    o.y = *reinterpret_cast<unsigned*>(&o1);
    o.z = *reinterpret_cast<unsigned*>(&o2);
    o.w = *reinterpret_cast<unsigned*>(&o3);
    *reinterpret_cast<uint4*>(&g_s[lout][(g << 6) + le]) = o;
}

// K6: layer-3 gather fused with final average.
// out = 0.25*(emb_fp32 + inv*(s1+s2) + rns*t3); inv*s_l == cur_l exactly.
// out layout [all; user; item] == [all; all].
__global__ void k_gather_final(const float* __restrict__ uw,
                               const float* __restrict__ iw,
                               float* __restrict__ out) {
    int g = blockIdx.x * 32 + (threadIdx.x >> 3);
    if (g >= NN) return;
    int le = (threadIdx.x & 7) << 3;
    const __half* __restrict__ in = g_s[2];
    int end = g_rowstart[g];
    int p   = end - g_degi[g];
    __half2 z = __float2half2_rn(0.0f);
    __half2 pA0=z,pA1=z,pA2=z,pA3=z, pB0=z,pB1=z,pB2=z,pB3=z;
    for (; p + 4 <= end; p += 4) {
        int s0 = g_csr[p],     s1 = g_csr[p + 1];
        int s2 = g_csr[p + 2], s3 = g_csr[p + 3];
        EDGE(s0, pA0, pA1, pA2, pA3) EDGE(s1, pB0, pB1, pB2, pB3)
        EDGE(s2, pA0, pA1, pA2, pA3) EDGE(s3, pB0, pB1, pB2, pB3)
    }
    for (; p < end; ++p) { int s0 = g_csr[p]; EDGE(s0, pA0, pA1, pA2, pA3) }

    float r   = g_rns[g];          // rns[d]
    float inv = g_inv[g];          // sqrt(deg) (0 if deg==0)
    int i = (g << 6) + le;
    const float* emb = (g < NU) ? &uw[i] : &iw[i - NU * DIM];
    float4 e0 = *reinterpret_cast<const float4*>(emb);
    float4 e1 = *reinterpret_cast<const float4*>(emb + 4);
    uint4 r1 = *reinterpret_cast<const uint4*>(&g_s[1][i]);
    uint4 r2 = *reinterpret_cast<const uint4*>(&g_s[2][i]);
    float2 s1a = __half22float2(*reinterpret_cast<__half2*>(&r1.x));
    float2 s1b = __half22float2(*reinterpret_cast<__half2*>(&r1.y));
    float2 s1c = __half22float2(*reinterpret_cast<__half2*>(&r1.z));
    float2 s1d = __half22float2(*reinterpret_cast<__half2*>(&r1.w));
    float2 s2a = __half22float2(*reinterpret_cast<__half2*>(&r2.x));
    float2 s2b = __half22float2(*reinterpret_cast<__half2*>(&r2.y));
    float2 s2c = __half22float2(*reinterpret_cast<__half2*>(&r2.z));
    float2 s2d = __half22float2(*reinterpret_cast<__half2*>(&r2.w));
    float2 tA, tB;
    tA = __half22float2(pA0); tB = __half22float2(pB0);
    float t0 = tA.x + tB.x, t1 = tA.y + tB.y;
    tA = __half22float2(pA1); tB = __half22float2(pB1);
    float t2 = tA.x + tB.x, t3 = tA.y + tB.y;
    tA = __half22float2(pA2); tB = __half22float2(pB2);
    float t4 = tA.x + tB.x, t5 = tA.y + tB.y;
    tA = __half22float2(pA3); tB = __half22float2(pB3);
    float t6 = tA.x + tB.x, t7 = tA.y + tB.y;
    float4 v0 = make_float4(0.25f * (e0.x + inv * (s1a.x + s2a.x) + r * t0),
                            0.25f * (e0.y + inv * (s1a.y + s2a.y) + r * t1),
                            0.25f * (e0.z + inv * (s1b.x + s2b.x) + r * t2),
                            0.25f * (e0.w + inv * (s1b.y + s2b.y) + r * t3));
    float4 v1 = make_float4(0.25f * (e1.x + inv * (s1c.x + s2c.x) + r * t4),
                            0.25f * (e1.y + inv * (s1c.y + s2c.y) + r * t5),
                            0.25f * (e1.z + inv * (s1d.x + s2d.x) + r * t6),
                            0.25f * (e1.w + inv * (s1d.y + s2d.y) + r * t7));
    *reinterpret_cast<float4*>(&out[i])            = v0;
    *reinterpret_cast<float4*>(&out[i + 4])        = v1;
    *reinterpret_cast<float4*>(&out[NALL + i])     = v0;
    *reinterpret_cast<float4*>(&out[NALL + i + 4]) = v1;
}

extern "C" void kernel_launch(void* const* d_in, const int* in_sizes, int n_in,
                              void* d_out, int out_size) {
    const int*   ei = (const int*)d_in[0];      // [2, NE] int32
    const float* uw = (const float*)d_in[1];    // [NU, 64]
    const float* iw = (const float*)d_in[2];    // [NI, 64]
    float*      out = (float*)d_out;            // [2*NALL] floats

    const int T = 256;
    int g_edge = (NE + T - 1) / T;              // NE > NV8, covers both sides
    int g_node = (NN + T - 1) / T;
    int g_gath = (NN + 31) / 32;                // 32 rows per 256-thread block

    k_zero<<<g_node, T>>>();
    k_deg<<<g_edge, T>>>(ei);
    k_alloc<<<NBLK, SCAN_B>>>();
    k_fillscale<<<g_edge, T>>>(ei, uw, iw);     // CSR fill + s0 pre-scale

    k_gather<<<g_gath, T>>>(0, 1);              // layer 1: s0 -> s1
    k_gather<<<g_gath, T>>>(1, 2);              // layer 2: s1 -> s2
    k_gather_final<<<g_gath, T>>>(uw, iw, out); // layer 3 + average + dup
}